// round 4
// baseline (speedup 1.0000x reference)
#include <cuda_runtime.h>
#include <cstdint>

#define NCTA 128
#define TPB  256
#define HDIM 1024

// Exchange: one tagged u64 per h element = {tag:32 | fp32 bits}
__device__ unsigned long long g_hbuf[2][HDIM];
__device__ float g_xg[4 * HDIM];

// ---------------- PTX helpers ----------------
__device__ __forceinline__ unsigned long long ld_relaxed_u64(const unsigned long long* p) {
    unsigned long long v;
    asm volatile("ld.relaxed.gpu.global.u64 %0, [%1];" : "=l"(v) : "l"(p));
    return v;
}
__device__ __forceinline__ void st_relaxed_u64(unsigned long long* p, unsigned long long v) {
    asm volatile("st.relaxed.gpu.global.u64 [%0], %1;" :: "l"(p), "l"(v) : "memory");
}
__device__ __forceinline__ unsigned long long fma2(unsigned long long a, unsigned long long b,
                                                   unsigned long long c) {
    unsigned long long d;
    asm("fma.rn.f32x2 %0, %1, %2, %3;" : "=l"(d) : "l"(a), "l"(b), "l"(c));
    return d;
}
__device__ __forceinline__ void lds_v2_u64(unsigned addr, unsigned long long& a,
                                           unsigned long long& b) {
    asm volatile("ld.shared.v2.u64 {%0, %1}, [%2];" : "=l"(a), "=l"(b) : "r"(addr));
}
__device__ __forceinline__ float f2sum(unsigned long long v) {
    return __uint_as_float((unsigned)v) + __uint_as_float((unsigned)(v >> 32));
}
__device__ __forceinline__ float tanh_acc(float x) {
    float e = __expf(2.0f * x);
    return 1.0f - 2.0f / (e + 1.0f);
}

// ---------------- x_gates = x @ W_ih.T + b_ih + b_hh ----------------
__global__ void xgates_kernel(const float* __restrict__ x, const float* __restrict__ Wih,
                              const float* __restrict__ bih, const float* __restrict__ bhh) {
    int lane = threadIdx.x & 31;
    int row  = blockIdx.x * 8 + (threadIdx.x >> 5);
    const float4* wr = (const float4*)(Wih + (size_t)row * HDIM);
    const float4* xr = (const float4*)x;
    float acc = 0.f;
    #pragma unroll
    for (int i = 0; i < 8; i++) {
        float4 w4 = wr[i * 32 + lane];
        float4 x4 = xr[i * 32 + lane];
        acc += w4.x * x4.x + w4.y * x4.y + w4.z * x4.z + w4.w * x4.w;
    }
    #pragma unroll
    for (int off = 16; off; off >>= 1) acc += __shfl_xor_sync(0xffffffffu, acc, off);
    if (lane == 0) g_xg[row] = acc + bih[row] + bhh[row];
}

// ---------------- persistent LSTM rollout ----------------
// 128 CTAs x 256 threads (8 warps). Warp w owns h element E = cta*8 + w and
// ALL FOUR gate rows {g*1024+E}. Lane l holds W[row][4l+128j..+3] for j=0..7
// (128 weight floats = 128 regs). After a 5-level butterfly every lane has all
// 4 gate sums; lanes 0..3 each apply one activation (branch-free form), lane 0
// combines via 3 shfls, updates c, and publishes the tagged fp32 h directly.
// One __syncthreads per step; no cross-warp funnel of any kind.
__global__ void __launch_bounds__(TPB, 1)
lstm_kernel(const float* __restrict__ Whh, float* __restrict__ out, int N) {
    __shared__ float h_sm[2][HDIM];   // double buffer

    const int tid  = threadIdx.x;
    const int lane = tid & 31;
    const int warp = tid >> 5;
    const int cta  = blockIdx.x;
    const int E    = cta * 8 + warp;  // owned h element

    // Pin the 4 gate rows of element E: w[gate][j], 16B per lane per (gate,j).
    ulonglong2 w[4][8];
    #pragma unroll
    for (int g = 0; g < 4; g++) {
        const float* base = Whh + (size_t)(g * HDIM + E) * HDIM + 4 * lane;
        #pragma unroll
        for (int j = 0; j < 8; j++)
            w[g][j] = *(const ulonglong2*)(base + j * 128);
    }
    // x-gate biases for this element (all lanes hold copies; only lane ops use).
    float xg0 = g_xg[0 * HDIM + E];
    float xg1 = g_xg[1 * HDIM + E];
    float xg2 = g_xg[2 * HDIM + E];
    float xg3 = g_xg[3 * HDIM + E];

    const unsigned hbase = (unsigned)__cvta_generic_to_shared(&h_sm[0][0]);
    // Activation constants: lane 2 -> tanh form, others -> sigmoid form.
    const float gam = (lane == 2) ? 2.f : -1.f;

    float c_state = 0.f;  // live in lane 0

    for (int t = 0; t < N; t++) {
        const int buf = t & 1;

        // ---- acquire h(t): 4 tagged u64 polls per thread, issued in parallel ----
        if (t == 0) {
            *(float4*)&h_sm[0][4 * tid] = make_float4(0.f, 0.f, 0.f, 0.f);
        } else {
            const unsigned long long* bp = g_hbuf[buf] + 4 * tid;
            const unsigned tag = (unsigned)t;
            unsigned long long v0 = ld_relaxed_u64(bp + 0);
            unsigned long long v1 = ld_relaxed_u64(bp + 1);
            unsigned long long v2 = ld_relaxed_u64(bp + 2);
            unsigned long long v3 = ld_relaxed_u64(bp + 3);
            while (((unsigned)(v0 >> 32) != tag) | ((unsigned)(v1 >> 32) != tag) |
                   ((unsigned)(v2 >> 32) != tag) | ((unsigned)(v3 >> 32) != tag)) {
                if ((unsigned)(v0 >> 32) != tag) v0 = ld_relaxed_u64(bp + 0);
                if ((unsigned)(v1 >> 32) != tag) v1 = ld_relaxed_u64(bp + 1);
                if ((unsigned)(v2 >> 32) != tag) v2 = ld_relaxed_u64(bp + 2);
                if ((unsigned)(v3 >> 32) != tag) v3 = ld_relaxed_u64(bp + 3);
            }
            float4 f4 = make_float4(__uint_as_float((unsigned)v0),
                                    __uint_as_float((unsigned)v1),
                                    __uint_as_float((unsigned)v2),
                                    __uint_as_float((unsigned)v3));
            *(float4*)&h_sm[buf][4 * tid] = f4;
        }
        __syncthreads();   // the only barrier per step

        // ---- full matvec for 4 gate rows of element E ----
        const unsigned myb = hbase + (unsigned)(buf * 4096 + lane * 16);
        unsigned long long a0 = 0ull, a1 = 0ull, a2 = 0ull, a3 = 0ull;
        #pragma unroll
        for (int j = 0; j < 8; j++) {
            unsigned long long hA, hB;
            lds_v2_u64(myb + (unsigned)(j * 512), hA, hB);
            a0 = fma2(w[0][j].x, hA, a0);  a0 = fma2(w[0][j].y, hB, a0);
            a1 = fma2(w[1][j].x, hA, a1);  a1 = fma2(w[1][j].y, hB, a1);
            a2 = fma2(w[2][j].x, hA, a2);  a2 = fma2(w[2][j].y, hB, a2);
            a3 = fma2(w[3][j].x, hA, a3);  a3 = fma2(w[3][j].y, hB, a3);
        }
        float s0 = f2sum(a0), s1 = f2sum(a1), s2 = f2sum(a2), s3 = f2sum(a3);
        #pragma unroll
        for (int off = 16; off; off >>= 1) {
            s0 += __shfl_xor_sync(0xffffffffu, s0, off);
            s1 += __shfl_xor_sync(0xffffffffu, s1, off);
            s2 += __shfl_xor_sync(0xffffffffu, s2, off);
            s3 += __shfl_xor_sync(0xffffffffu, s3, off);
        }
        // every lane now holds the fully-reduced s0..s3

        // ---- distributed activations: lane g handles gate g (branch-free) ----
        float s = (lane == 0) ? s0 + xg0
                : (lane == 1) ? s1 + xg1
                : (lane == 2) ? s2 + xg2
                :               s3 + xg3;
        float e  = __expf(gam * s);
        float r  = 1.0f / (1.0f + e);
        float a  = (lane == 2) ? fmaf(-2.f, r, 1.f) : r;  // tanh vs sigmoid

        float i_ = __shfl_sync(0xffffffffu, a, 0);
        float f_ = __shfl_sync(0xffffffffu, a, 1);
        float g_ = __shfl_sync(0xffffffffu, a, 2);
        float o_ = __shfl_sync(0xffffffffu, a, 3);

        if (lane == 0) {
            c_state = f_ * c_state + i_ * g_;
            float hv = o_ * tanh_acc(c_state);
            unsigned long long pv =
                ((unsigned long long)(unsigned)(t + 1) << 32) |
                (unsigned long long)__float_as_uint(hv);
            st_relaxed_u64(&g_hbuf[(t + 1) & 1][E], pv);
            out[(size_t)t * HDIM + E] = hv;
        }
        // No trailing barrier: h_sm buffer reuse at t+2 is ordered by the
        // publish->poll causal chain (a tag t+2 observation implies every CTA
        // passed barrier t+1, hence finished all h_sm[buf] reads of step t).
    }
}

extern "C" void kernel_launch(void* const* d_in, const int* in_sizes, int n_in,
                              void* d_out, int out_size) {
    const float* x   = (const float*)d_in[0];
    const float* Wih = (const float*)d_in[1];
    const float* Whh = (const float*)d_in[2];
    const float* bih = (const float*)d_in[3];
    const float* bhh = (const float*)d_in[4];
    float* out = (float*)d_out;
    const int N = out_size / HDIM;

    xgates_kernel<<<512, 256>>>(x, Wih, bih, bhh);
    lstm_kernel<<<NCTA, TPB>>>(Whh, out, N);
}

// round 8
// speedup vs baseline: 1.2761x; 1.2761x over previous
#include <cuda_runtime.h>
#include <cstdint>

#define NCTA 128
#define TPB  512
#define HDIM 1024

// Exchange: one tagged u64 per h element = {tag:32 | fp32 bits}
__device__ unsigned long long g_hbuf[2][HDIM];
__device__ float g_xg[4 * HDIM];

// ---------------- PTX helpers ----------------
__device__ __forceinline__ unsigned long long ld_relaxed_u64(const unsigned long long* p) {
    unsigned long long v;
    asm volatile("ld.relaxed.gpu.global.u64 %0, [%1];" : "=l"(v) : "l"(p));
    return v;
}
__device__ __forceinline__ void st_relaxed_u64(unsigned long long* p, unsigned long long v) {
    asm volatile("st.relaxed.gpu.global.u64 [%0], %1;" :: "l"(p), "l"(v) : "memory");
}
__device__ __forceinline__ unsigned long long lds_vol_u64(unsigned a) {
    unsigned long long v;
    asm volatile("ld.volatile.shared.u64 %0, [%1];" : "=l"(v) : "r"(a));
    return v;
}
__device__ __forceinline__ void sts_vol_u64(unsigned a, unsigned long long v) {
    asm volatile("st.volatile.shared.u64 [%0], %1;" :: "r"(a), "l"(v));
}
__device__ __forceinline__ unsigned long long fma2(unsigned long long a, unsigned long long b,
                                                   unsigned long long c) {
    unsigned long long d;
    asm("fma.rn.f32x2 %0, %1, %2, %3;" : "=l"(d) : "l"(a), "l"(b), "l"(c));
    return d;
}
__device__ __forceinline__ void lds_v2_u64(unsigned addr, unsigned long long& a,
                                           unsigned long long& b) {
    asm volatile("ld.shared.v2.u64 {%0, %1}, [%2];" : "=l"(a), "=l"(b) : "r"(addr));
}
__device__ __forceinline__ float f2sum(unsigned long long v) {
    return __uint_as_float((unsigned)v) + __uint_as_float((unsigned)(v >> 32));
}
__device__ __forceinline__ float sigf(float x) { return 1.0f / (1.0f + __expf(-x)); }
__device__ __forceinline__ float tanh_acc(float x) {
    float e = __expf(2.0f * x);
    return 1.0f - 2.0f / (e + 1.0f);
}

// ---------------- x_gates = x @ W_ih.T + b_ih + b_hh ----------------
__global__ void xgates_kernel(const float* __restrict__ x, const float* __restrict__ Wih,
                              const float* __restrict__ bih, const float* __restrict__ bhh) {
    int lane = threadIdx.x & 31;
    int row  = blockIdx.x * 8 + (threadIdx.x >> 5);
    const float4* wr = (const float4*)(Wih + (size_t)row * HDIM);
    const float4* xr = (const float4*)x;
    float acc = 0.f;
    #pragma unroll
    for (int i = 0; i < 8; i++) {
        float4 w4 = wr[i * 32 + lane];
        float4 x4 = xr[i * 32 + lane];
        acc += w4.x * x4.x + w4.y * x4.y + w4.z * x4.z + w4.w * x4.w;
    }
    #pragma unroll
    for (int off = 16; off; off >>= 1) acc += __shfl_xor_sync(0xffffffffu, acc, off);
    if (lane == 0) g_xg[row] = acc + bih[row] + bhh[row];
}

// ---------------- persistent LSTM rollout ----------------
// 128 CTAs x 512 threads (16 warps). Element e = warp>>1 (E = cta*8+e);
// half hf = warp&1. Half-0 computes gate rows {E, H+E} (i,f); half-1 computes
// {2H+E, 3H+E} (g,o) and applies its own activations. Half-1 lane0 hands
// (tanh g, sig o) to half-0 lane0 via two tagged SMEM words; half-0 lane0
// updates c, forms h, publishes the tagged fp32 h to L2 and writes out.
// One __syncthreads per step; partner handoff costs ~2 LDS polls, not a bar.
__global__ void __launch_bounds__(TPB, 1)
lstm_kernel(const float* __restrict__ Whh, float* __restrict__ out, int N) {
    __shared__ float h_sm[2][HDIM];               // double buffer, 8KB
    __shared__ unsigned long long g_io[8][2];     // [elem][0]=tanh(g), [1]=sig(o), tagged

    const int tid  = threadIdx.x;
    const int lane = tid & 31;
    const int warp = tid >> 5;
    const int cta  = blockIdx.x;
    const int e    = warp >> 1;
    const int hf   = warp & 1;
    const int E    = cta * 8 + e;

    // Pin 2 gate rows: gates (2hf, 2hf+1) of element E. 64 weight floats/lane.
    const int gr0 = (2 * hf) * HDIM + E;
    const int gr1 = (2 * hf + 1) * HDIM + E;
    ulonglong2 w0[8], w1[8];
    #pragma unroll
    for (int j = 0; j < 8; j++) {
        w0[j] = *(const ulonglong2*)(Whh + (size_t)gr0 * HDIM + j * 128 + 4 * lane);
        w1[j] = *(const ulonglong2*)(Whh + (size_t)gr1 * HDIM + j * 128 + 4 * lane);
    }
    const float xgA = g_xg[gr0];
    const float xgB = g_xg[gr1];

    if (tid < 16) ((unsigned long long*)g_io)[tid] = 0ull;  // tag 0 never matches t+1

    const unsigned hbase  = (unsigned)__cvta_generic_to_shared(&h_sm[0][0]);
    const unsigned iobase = (unsigned)__cvta_generic_to_shared(&g_io[0][0]);

    float c_state = 0.f;  // live in half-0 lane 0

    for (int t = 0; t < N; t++) {
        const int buf = t & 1;

        // ---- acquire h(t): two tagged u64 polls per thread, issued in parallel ----
        if (t == 0) {
            *(float2*)&h_sm[0][2 * tid] = make_float2(0.f, 0.f);
        } else {
            const unsigned long long* bp = g_hbuf[buf] + 2 * tid;
            const unsigned tag = (unsigned)t;
            unsigned long long v0 = ld_relaxed_u64(bp + 0);
            unsigned long long v1 = ld_relaxed_u64(bp + 1);
            while (((unsigned)(v0 >> 32) != tag) | ((unsigned)(v1 >> 32) != tag)) {
                v0 = ld_relaxed_u64(bp + 0);
                v1 = ld_relaxed_u64(bp + 1);
            }
            *(float2*)&h_sm[buf][2 * tid] =
                make_float2(__uint_as_float((unsigned)v0), __uint_as_float((unsigned)v1));
        }
        __syncthreads();   // the only barrier per step

        // ---- matvec: 2 gate rows, packed f32x2 FMAs ----
        const unsigned myb = hbase + (unsigned)(buf * 4096 + lane * 16);
        unsigned long long a0 = 0ull, a1 = 0ull;
        #pragma unroll
        for (int j = 0; j < 8; j++) {
            unsigned long long hA, hB;
            lds_v2_u64(myb + (unsigned)(j * 512), hA, hB);
            a0 = fma2(w0[j].x, hA, a0);  a0 = fma2(w0[j].y, hB, a0);
            a1 = fma2(w1[j].x, hA, a1);  a1 = fma2(w1[j].y, hB, a1);
        }
        float s0 = f2sum(a0), s1 = f2sum(a1);
        #pragma unroll
        for (int off = 16; off; off >>= 1) {
            s0 += __shfl_xor_sync(0xffffffffu, s0, off);
            s1 += __shfl_xor_sync(0xffffffffu, s1, off);
        }

        if (lane == 0) {
            const unsigned tag = (unsigned)(t + 1);
            const unsigned long long tg = ((unsigned long long)tag) << 32;
            const unsigned ioa = iobase + (unsigned)(e * 16);
            if (hf) {
                // gates g, o: activate here, hand off to partner warp
                float g_ = tanh_acc(s0 + xgA);
                float o_ = sigf(s1 + xgB);
                sts_vol_u64(ioa,     tg | (unsigned long long)__float_as_uint(g_));
                sts_vol_u64(ioa + 8, tg | (unsigned long long)__float_as_uint(o_));
            } else {
                // gates i, f: activate while partner works, then join
                float i_ = sigf(s0 + xgA);
                float f_ = sigf(s1 + xgB);
                unsigned long long p0 = lds_vol_u64(ioa);
                while ((unsigned)(p0 >> 32) != tag) p0 = lds_vol_u64(ioa);
                unsigned long long p1 = lds_vol_u64(ioa + 8);
                while ((unsigned)(p1 >> 32) != tag) p1 = lds_vol_u64(ioa + 8);
                float g_ = __uint_as_float((unsigned)p0);
                float o_ = __uint_as_float((unsigned)p1);
                c_state = f_ * c_state + i_ * g_;
                float hv = o_ * tanh_acc(c_state);
                st_relaxed_u64(&g_hbuf[(t + 1) & 1][E],
                               tg | (unsigned long long)__float_as_uint(hv));
                out[(size_t)t * HDIM + E] = hv;
            }
        }
        // No trailing barrier: h_sm reuse at t+2 is ordered by the publish->poll
        // causal chain; g_io words are exact-tag matched (monotone tags, zeroed
        // once at start; cross-replay staleness benign by determinism).
    }
}

extern "C" void kernel_launch(void* const* d_in, const int* in_sizes, int n_in,
                              void* d_out, int out_size) {
    const float* x   = (const float*)d_in[0];
    const float* Wih = (const float*)d_in[1];
    const float* Whh = (const float*)d_in[2];
    const float* bih = (const float*)d_in[3];
    const float* bhh = (const float*)d_in[4];
    float* out = (float*)d_out;
    const int N = out_size / HDIM;

    xgates_kernel<<<512, 256>>>(x, Wih, bih, bhh);
    lstm_kernel<<<NCTA, TPB>>>(Whh, out, N);
}

// round 9
// speedup vs baseline: 4.0358x; 3.1625x over previous
#include <cuda_runtime.h>
#include <cstdint>

#define NCTA 128
#define TPB  512
#define HDIM 1024

// Exchange: one tagged u64 per h element = {tag:32 | fp32 bits}
__device__ unsigned long long g_hbuf[2][HDIM];
__device__ float g_xg[4 * HDIM];

// ---------------- PTX helpers ----------------
__device__ __forceinline__ unsigned long long ld_relaxed_u64(const unsigned long long* p) {
    unsigned long long v;
    asm volatile("ld.relaxed.gpu.global.u64 %0, [%1];" : "=l"(v) : "l"(p));
    return v;
}
__device__ __forceinline__ void st_relaxed_u64(unsigned long long* p, unsigned long long v) {
    asm volatile("st.relaxed.gpu.global.u64 [%0], %1;" :: "l"(p), "l"(v) : "memory");
}
__device__ __forceinline__ unsigned long long fma2(unsigned long long a, unsigned long long b,
                                                   unsigned long long c) {
    unsigned long long d;
    asm("fma.rn.f32x2 %0, %1, %2, %3;" : "=l"(d) : "l"(a), "l"(b), "l"(c));
    return d;
}
__device__ __forceinline__ void lds_v2_u64(unsigned addr, unsigned long long& a,
                                           unsigned long long& b) {
    asm volatile("ld.shared.v2.u64 {%0, %1}, [%2];" : "=l"(a), "=l"(b) : "r"(addr));
}
__device__ __forceinline__ float f2sum(unsigned long long v) {
    return __uint_as_float((unsigned)v) + __uint_as_float((unsigned)(v >> 32));
}
__device__ __forceinline__ float sigf(float x) { return 1.0f / (1.0f + __expf(-x)); }
__device__ __forceinline__ float tanh_acc(float x) {
    float e = __expf(2.0f * x);
    return 1.0f - 2.0f / (e + 1.0f);
}

// ---------------- x_gates = x @ W_ih.T + b_ih + b_hh ----------------
__global__ void xgates_kernel(const float* __restrict__ x, const float* __restrict__ Wih,
                              const float* __restrict__ bih, const float* __restrict__ bhh) {
    int lane = threadIdx.x & 31;
    int row  = blockIdx.x * 8 + (threadIdx.x >> 5);
    const float4* wr = (const float4*)(Wih + (size_t)row * HDIM);
    const float4* xr = (const float4*)x;
    float acc = 0.f;
    #pragma unroll
    for (int i = 0; i < 8; i++) {
        float4 w4 = wr[i * 32 + lane];
        float4 x4 = xr[i * 32 + lane];
        acc += w4.x * x4.x + w4.y * x4.y + w4.z * x4.z + w4.w * x4.w;
    }
    #pragma unroll
    for (int off = 16; off; off >>= 1) acc += __shfl_xor_sync(0xffffffffu, acc, off);
    if (lane == 0) g_xg[row] = acc + bih[row] + bhh[row];
}

// ---------------- persistent LSTM rollout ----------------
// 128 CTAs x 512 threads (16 warps). CTA owns h elems [8c,8c+8) -> 32 gate rows.
// Warp w: q=w&7 -> local rows [4q,4q+4); hh=w>>3 -> h half [512*hh, 512*hh+512).
// Each warp: 4 rows x half-h = 2048 MACs, 64 weight floats/lane (proven budget),
// reads only 2KB of h_sm per step (crossbar halved vs R1).
// Sync per step: bar1 (after poll fill) and bar2 (before funnel) -- NO spin
// polls anywhere inside the CTA (R3/R8 lesson). tid<8 funnel combines the two
// half partials per row from plain SMEM, applies activations, publishes h.
__global__ void __launch_bounds__(TPB, 1)
lstm_kernel(const float* __restrict__ Whh, float* __restrict__ out, int N) {
    __shared__ float h_sm[2][HDIM];        // double buffer, 8KB
    __shared__ float g_part[32][2];        // [local row][half] raw partial sums

    const int tid  = threadIdx.x;
    const int lane = tid & 31;
    const int warp = tid >> 5;
    const int cta  = blockIdx.x;
    const int q    = warp & 7;             // row group
    const int hh   = warp >> 3;            // h half

    // Pin weights: rows rl = 4q+r (gate=rl>>3, elem=rl&7), half hh.
    // w[r][j] = 16B: W[gr][hh*512 + j*128 + 4*lane .. +3], j=0..3 -> 64 floats.
    ulonglong2 w[4][4];
    #pragma unroll
    for (int r = 0; r < 4; r++) {
        int rl = 4 * q + r;
        int gr = (rl >> 3) * HDIM + cta * 8 + (rl & 7);
        const float* base = Whh + (size_t)gr * HDIM + hh * 512 + 4 * lane;
        #pragma unroll
        for (int j = 0; j < 4; j++)
            w[r][j] = *(const ulonglong2*)(base + j * 128);
    }

    // Funnel threads preload their 4 gate biases.
    float xg4[4] = {0.f, 0.f, 0.f, 0.f};
    if (tid < 8) {
        #pragma unroll
        for (int g = 0; g < 4; g++) xg4[g] = g_xg[g * HDIM + cta * 8 + tid];
    }

    const unsigned hbase = (unsigned)__cvta_generic_to_shared(&h_sm[0][0]);

    float c_state = 0.f;  // live in tid<8

    for (int t = 0; t < N; t++) {
        const int buf = t & 1;

        // ---- acquire h(t): both loads issued up front, serial retry loops ----
        if (t == 0) {
            *(float2*)&h_sm[0][2 * tid] = make_float2(0.f, 0.f);
        } else {
            const unsigned long long* bp = g_hbuf[buf] + 2 * tid;
            const unsigned tag = (unsigned)t;
            unsigned long long v0 = ld_relaxed_u64(bp + 0);
            unsigned long long v1 = ld_relaxed_u64(bp + 1);
            while ((unsigned)(v0 >> 32) != tag) v0 = ld_relaxed_u64(bp + 0);
            while ((unsigned)(v1 >> 32) != tag) v1 = ld_relaxed_u64(bp + 1);
            *(float2*)&h_sm[buf][2 * tid] =
                make_float2(__uint_as_float((unsigned)v0), __uint_as_float((unsigned)v1));
        }
        __syncthreads();   // bar1

        // ---- matvec: 4 rows over this warp's h half ----
        const unsigned myb = hbase + (unsigned)(buf * 4096 + hh * 2048 + lane * 16);
        unsigned long long a0 = 0ull, a1 = 0ull, a2 = 0ull, a3 = 0ull;
        #pragma unroll
        for (int j = 0; j < 4; j++) {
            unsigned long long hA, hB;
            lds_v2_u64(myb + (unsigned)(j * 512), hA, hB);
            a0 = fma2(w[0][j].x, hA, a0);  a0 = fma2(w[0][j].y, hB, a0);
            a1 = fma2(w[1][j].x, hA, a1);  a1 = fma2(w[1][j].y, hB, a1);
            a2 = fma2(w[2][j].x, hA, a2);  a2 = fma2(w[2][j].y, hB, a2);
            a3 = fma2(w[3][j].x, hA, a3);  a3 = fma2(w[3][j].y, hB, a3);
        }
        float s0 = f2sum(a0), s1 = f2sum(a1), s2 = f2sum(a2), s3 = f2sum(a3);
        #pragma unroll
        for (int off = 16; off; off >>= 1) {
            s0 += __shfl_xor_sync(0xffffffffu, s0, off);
            s1 += __shfl_xor_sync(0xffffffffu, s1, off);
            s2 += __shfl_xor_sync(0xffffffffu, s2, off);
            s3 += __shfl_xor_sync(0xffffffffu, s3, off);
        }
        if (lane == 0) {
            g_part[4 * q + 0][hh] = s0;
            g_part[4 * q + 1][hh] = s1;
            g_part[4 * q + 2][hh] = s2;
            g_part[4 * q + 3][hh] = s3;
        }
        __syncthreads();   // bar2

        // ---- funnel: 8 threads, combine halves + activations + publish ----
        if (tid < 8) {
            float gs[4];
            #pragma unroll
            for (int g = 0; g < 4; g++) {
                float2 p = *(const float2*)&g_part[g * 8 + tid][0];
                gs[g] = p.x + p.y + xg4[g];
            }
            float i_ = sigf(gs[0]);
            float f_ = sigf(gs[1]);
            float g_ = tanh_acc(gs[2]);
            float o_ = sigf(gs[3]);
            c_state = f_ * c_state + i_ * g_;
            float hv = o_ * tanh_acc(c_state);

            unsigned long long pv =
                ((unsigned long long)(unsigned)(t + 1) << 32) |
                (unsigned long long)__float_as_uint(hv);
            st_relaxed_u64(&g_hbuf[(t + 1) & 1][cta * 8 + tid], pv);
            out[(size_t)t * HDIM + cta * 8 + tid] = hv;
        }
        // h_sm[buf] reuse at t+2 and g_part reuse at t+1 are both ordered by
        // per-thread program order + bar1/bar2 (no cross-CTA argument needed).
    }
}

extern "C" void kernel_launch(void* const* d_in, const int* in_sizes, int n_in,
                              void* d_out, int out_size) {
    const float* x   = (const float*)d_in[0];
    const float* Wih = (const float*)d_in[1];
    const float* Whh = (const float*)d_in[2];
    const float* bih = (const float*)d_in[3];
    const float* bhh = (const float*)d_in[4];
    float* out = (float*)d_out;
    const int N = out_size / HDIM;

    xgates_kernel<<<512, 256>>>(x, Wih, bih, bhh);
    lstm_kernel<<<NCTA, TPB>>>(Whh, out, N);
}